// round 14
// baseline (speedup 1.0000x reference)
#include <cuda_runtime.h>
#include <cuda_fp16.h>

#define NE 1200000
#define NN 50000
#define DF 64
#define HID 32

__device__ int g_idx_is64;

// fp16 per-node partials, one 128-byte line per node:
//   bytes [0,64)   : A'[n] = x[n]@W1[0:64] + b1   (32 fp16)
//   bytes [64,128) : B[n]  = x[n]@W1[64:128]      (32 fp16)
__device__ __align__(128) __half g_ABh[NN * 64];   // 6.4 MB (L2-resident)

// Hot weight matrix on the constant port.
__constant__ float cW2[HID * HID];      // 4 KB

// ---- packed f32x2 helpers (Blackwell sm_103a) ----
__device__ __forceinline__ unsigned long long pk2(float a, float b) {
    unsigned long long r;
    asm("mov.b64 %0, {%1, %2};" : "=l"(r) : "f"(a), "f"(b));
    return r;
}
__device__ __forceinline__ void upk2(unsigned long long v, float& a, float& b) {
    asm("mov.b64 {%0, %1}, %2;" : "=f"(a), "=f"(b) : "l"(v));
}
__device__ __forceinline__ unsigned long long fma2(unsigned long long a,
                                                   unsigned long long b,
                                                   unsigned long long c) {
    unsigned long long d;
    asm("fma.rn.f32x2 %0, %1, %2, %3;" : "=l"(d) : "l"(a), "l"(b), "l"(c));
    return d;
}

// Pre-pass (unchanged from R12): per node per half; W1 staged in shared.
__global__ __launch_bounds__(256)
void node_gemm_kernel(const float4* __restrict__ x4,
                      const float* __restrict__ W1g,
                      const float* __restrict__ b1g,
                      const long long* __restrict__ ei,
                      float* __restrict__ out) {
    __shared__ __align__(16) float sW1[DF * HID];   // 8 KB
    int half = blockIdx.y;

    for (int i = threadIdx.x; i < DF * HID / 4; i += blockDim.x)
        ((float4*)sW1)[i] = ((const float4*)W1g)[half * (DF * HID / 4) + i];
    __syncthreads();

    int node = blockIdx.x * blockDim.x + threadIdx.x;
    if (half == 0 && node < NN) out[node] = 0.0f;
    if (half == 0 && node == 0) {
        int ok64 = 1;
        for (int k = 0; k < 8; k++) {
            long long v = ei[k];
            if (v < 0 || v >= NN) ok64 = 0;
        }
        g_idx_is64 = ok64;
    }
    if (node >= NN) return;

    unsigned long long acc[16];
    if (half == 0) {
        const float2* b1p = (const float2*)b1g;
        #pragma unroll
        for (int j = 0; j < 16; j++) {
            float2 b = __ldg(b1p + j);
            acc[j] = pk2(b.x, b.y);
        }
    } else {
        #pragma unroll
        for (int j = 0; j < 16; j++) acc[j] = 0ULL;
    }

    const float4* xp = x4 + (long)node * (DF / 4);
    #pragma unroll 4
    for (int q = 0; q < DF / 4; q++) {
        float4 xv = __ldg(xp + q);
        float vals[4] = {xv.x, xv.y, xv.z, xv.w};
        #pragma unroll
        for (int c = 0; c < 4; c++) {
            int k = q * 4 + c;
            unsigned long long xx = pk2(vals[c], vals[c]);
            const ulonglong2* wrow = (const ulonglong2*)(sW1 + k * 32);
            #pragma unroll
            for (int m = 0; m < 8; m++) {
                ulonglong2 wv = wrow[m];
                acc[2 * m]     = fma2(xx, wv.x, acc[2 * m]);
                acc[2 * m + 1] = fma2(xx, wv.y, acc[2 * m + 1]);
            }
        }
    }

    __half2 hv[16];
    #pragma unroll
    for (int j = 0; j < 16; j++) {
        float a, b;
        upk2(acc[j], a, b);
        hv[j] = __floats2half2_rn(a, b);
    }
    uint4* dst = (uint4*)((char*)g_ABh + (long)node * 128 + half * 64);
    const uint4* src = (const uint4*)hv;
    #pragma unroll
    for (int m = 0; m < 4; m++) dst[m] = src[m];
}

// Edge kernel, 2 edges/thread, LOW-REGISTER variant targeting 4 blocks/SM:
//  - gathers folded per edge (8-LDG bursts, raw regs peak 32)
//  - layer-2 split into 4 column-passes of 8 columns (g = 16 regs/pass),
//    each pass folded through relu*W3 immediately; LDC/FMA totals unchanged
//    and still shared across the edge pair.
__global__ __launch_bounds__(256, 4)
void edge_mlp_kernel(const void* __restrict__ ei_raw,
                     const float* __restrict__ u,
                     const float* __restrict__ b2g,
                     const float* __restrict__ W3g,
                     const float* __restrict__ b3g,
                     float* __restrict__ out)
{
    long e0 = (long)blockIdx.x * 512 + threadIdx.x;
    long e1 = e0 + 256;
    if (e0 >= NE) return;
    bool v1 = (e1 < NE);
    if (!v1) e1 = e0;   // duplicate work; atomic suppressed below

    int row0, col0, row1, col1;
    if (g_idx_is64) {
        const long long* ei = (const long long*)ei_raw;
        row0 = (int)ei[e0];      row1 = (int)ei[e1];
        col0 = (int)ei[NE + e0]; col1 = (int)ei[NE + e1];
    } else {
        const int* ei = (const int*)ei_raw;
        row0 = ei[e0];      row1 = ei[e1];
        col0 = ei[NE + e0]; col1 = ei[NE + e1];
    }
    row0 = min(max(row0, 0), NN - 1); col0 = min(max(col0, 0), NN - 1);
    row1 = min(max(row1, 0), NN - 1); col1 = min(max(col1, 0), NN - 1);

    float uc0 = __ldg(u + col0);
    float uc1 = __ldg(u + col1);

    const char* ab = (const char*)g_ABh;
    const __half2 z2 = __half2half2(__ushort_as_half(0));
    __half2 hh0[16], hh1[16];

    // edge 0 gather (8-LDG burst) + fold
    {
        const uint4* ap = (const uint4*)(ab + (long)row0 * 128);
        const uint4* bp = (const uint4*)(ab + (long)col0 * 128 + 64);
        uint4 ra[4], rb[4];
        #pragma unroll
        for (int m = 0; m < 4; m++) { ra[m] = __ldg(ap + m); rb[m] = __ldg(bp + m); }
        #pragma unroll
        for (int m = 0; m < 4; m++) {
            const __half2* ah = (const __half2*)&ra[m];
            const __half2* bh = (const __half2*)&rb[m];
            #pragma unroll
            for (int p = 0; p < 4; p++)
                hh0[m * 4 + p] = __hmax2(__hadd2(ah[p], bh[p]), z2);
        }
    }
    // edge 1 gather + fold (reuses raw registers)
    {
        const uint4* ap = (const uint4*)(ab + (long)row1 * 128);
        const uint4* bp = (const uint4*)(ab + (long)col1 * 128 + 64);
        uint4 ra[4], rb[4];
        #pragma unroll
        for (int m = 0; m < 4; m++) { ra[m] = __ldg(ap + m); rb[m] = __ldg(bp + m); }
        #pragma unroll
        for (int m = 0; m < 4; m++) {
            const __half2* ah = (const __half2*)&ra[m];
            const __half2* bh = (const __half2*)&rb[m];
            #pragma unroll
            for (int p = 0; p < 4; p++)
                hh1[m * 4 + p] = __hmax2(__hadd2(ah[p], bh[p]), z2);
        }
    }

    float b3v = __ldg(b3g);
    float w0 = b3v, w1 = b3v;

    // 4 column passes of 8 output columns each.
    #pragma unroll
    for (int pass = 0; pass < 4; pass++) {
        unsigned long long g0[4], g1[4];
        {
            const float2* b2p = (const float2*)(b2g + pass * 8);
            #pragma unroll
            for (int j = 0; j < 4; j++) {
                float2 b = __ldg(b2p + j);
                unsigned long long bb = pk2(b.x, b.y);
                g0[j] = bb; g1[j] = bb;
            }
        }

        #pragma unroll 2
        for (int kk = 0; kk < 16; kk++) {
            float2 f0 = __half22float2(hh0[kk]);
            float2 f1 = __half22float2(hh1[kk]);
            {
                unsigned long long x0 = pk2(f0.x, f0.x);
                unsigned long long x1 = pk2(f1.x, f1.x);
                const ulonglong2* wr =
                    (const ulonglong2*)(cW2 + (2 * kk) * 32 + pass * 8);
                #pragma unroll
                for (int m = 0; m < 2; m++) {
                    ulonglong2 wv = wr[m];               // LDC.128, pair-shared
                    g0[2 * m]     = fma2(x0, wv.x, g0[2 * m]);
                    g0[2 * m + 1] = fma2(x0, wv.y, g0[2 * m + 1]);
                    g1[2 * m]     = fma2(x1, wv.x, g1[2 * m]);
                    g1[2 * m + 1] = fma2(x1, wv.y, g1[2 * m + 1]);
                }
            }
            {
                unsigned long long x0 = pk2(f0.y, f0.y);
                unsigned long long x1 = pk2(f1.y, f1.y);
                const ulonglong2* wr =
                    (const ulonglong2*)(cW2 + (2 * kk + 1) * 32 + pass * 8);
                #pragma unroll
                for (int m = 0; m < 2; m++) {
                    ulonglong2 wv = wr[m];
                    g0[2 * m]     = fma2(x0, wv.x, g0[2 * m]);
                    g0[2 * m + 1] = fma2(x0, wv.y, g0[2 * m + 1]);
                    g1[2 * m]     = fma2(x1, wv.x, g1[2 * m]);
                    g1[2 * m + 1] = fma2(x1, wv.y, g1[2 * m + 1]);
                }
            }
        }

        // fold this pass through relu * W3
        #pragma unroll
        for (int j = 0; j < 4; j++) {
            float a, b;
            float2 w3 = __ldg((const float2*)(W3g + pass * 8) + j);
            upk2(g0[j], a, b);
            w0 = fmaf(fmaxf(a, 0.0f), w3.x, w0);
            w0 = fmaf(fmaxf(b, 0.0f), w3.y, w0);
            upk2(g1[j], a, b);
            w1 = fmaf(fmaxf(a, 0.0f), w3.x, w1);
            w1 = fmaf(fmaxf(b, 0.0f), w3.y, w1);
        }
    }

    atomicAdd(out + row0, w0 * uc0);
    if (v1) atomicAdd(out + row1, w1 * uc1);
}

extern "C" void kernel_launch(void* const* d_in, const int* in_sizes, int n_in,
                              void* d_out, int out_size) {
    const float* x  = (const float*)d_in[0];
    const void*  ei = d_in[1];
    const float* u  = (const float*)d_in[2];
    const float* W1 = (const float*)d_in[3];
    const float* b1 = (const float*)d_in[4];
    const float* W2 = (const float*)d_in[5];
    const float* b2 = (const float*)d_in[6];
    const float* W3 = (const float*)d_in[7];
    const float* b3 = (const float*)d_in[8];
    float* out = (float*)d_out;

    cudaMemcpyToSymbolAsync(cW2, W2, HID * HID * sizeof(float), 0,
                            cudaMemcpyDeviceToDevice, 0);

    dim3 gg((NN + 255) / 256, 2);
    node_gemm_kernel<<<gg, 256>>>((const float4*)x, W1, b1,
                                  (const long long*)ei, out);

    edge_mlp_kernel<<<(NE + 511) / 512, 256>>>(ei, u, b2, W3, b3, out);
}

// round 16
// speedup vs baseline: 1.2594x; 1.2594x over previous
#include <cuda_runtime.h>
#include <cuda_fp16.h>

#define NE 1200000
#define NN 50000
#define DF 64
#define HID 32
#define HSTR 80   // smem row stride (bytes): 16B-aligned, conflict-free for LDSM

__device__ int g_idx_is64;

// fp16 per-node partials, one 128-byte line per node:
//   bytes [0,64)   : A'[n] = x[n]@W1[0:64] + b1   (32 fp16)
//   bytes [64,128) : B[n]  = x[n]@W1[64:128]      (32 fp16)
__device__ __align__(128) __half g_ABh[NN * 64];   // 6.4 MB (L2-resident)

// ---- packed f32x2 helpers (node_gemm only) ----
__device__ __forceinline__ unsigned long long pk2(float a, float b) {
    unsigned long long r;
    asm("mov.b64 %0, {%1, %2};" : "=l"(r) : "f"(a), "f"(b));
    return r;
}
__device__ __forceinline__ void upk2(unsigned long long v, float& a, float& b) {
    asm("mov.b64 {%0, %1}, %2;" : "=f"(a), "=f"(b) : "l"(v));
}
__device__ __forceinline__ unsigned long long fma2(unsigned long long a,
                                                   unsigned long long b,
                                                   unsigned long long c) {
    unsigned long long d;
    asm("fma.rn.f32x2 %0, %1, %2, %3;" : "=l"(d) : "l"(a), "l"(b), "l"(c));
    return d;
}
__device__ __forceinline__ unsigned int smem_u32(const void* p) {
    unsigned int a;
    asm("{ .reg .u64 t; cvta.to.shared.u64 t, %1; cvt.u32.u64 %0, t; }"
        : "=r"(a) : "l"(p));
    return a;
}
__device__ __forceinline__ unsigned int h2u(__half2 h) {
    unsigned int u;
    memcpy(&u, &h, 4);
    return u;
}

// Pre-pass (unchanged from R12): per node per half; W1 staged in shared.
__global__ __launch_bounds__(256)
void node_gemm_kernel(const float4* __restrict__ x4,
                      const float* __restrict__ W1g,
                      const float* __restrict__ b1g,
                      const long long* __restrict__ ei,
                      float* __restrict__ out) {
    __shared__ __align__(16) float sW1[DF * HID];
    int half = blockIdx.y;

    for (int i = threadIdx.x; i < DF * HID / 4; i += blockDim.x)
        ((float4*)sW1)[i] = ((const float4*)W1g)[half * (DF * HID / 4) + i];
    __syncthreads();

    int node = blockIdx.x * blockDim.x + threadIdx.x;
    if (half == 0 && node < NN) out[node] = 0.0f;
    if (half == 0 && node == 0) {
        int ok64 = 1;
        for (int k = 0; k < 8; k++) {
            long long v = ei[k];
            if (v < 0 || v >= NN) ok64 = 0;
        }
        g_idx_is64 = ok64;
    }
    if (node >= NN) return;

    unsigned long long acc[16];
    if (half == 0) {
        const float2* b1p = (const float2*)b1g;
        #pragma unroll
        for (int j = 0; j < 16; j++) {
            float2 b = __ldg(b1p + j);
            acc[j] = pk2(b.x, b.y);
        }
    } else {
        #pragma unroll
        for (int j = 0; j < 16; j++) acc[j] = 0ULL;
    }

    const float4* xp = x4 + (long)node * (DF / 4);
    #pragma unroll 4
    for (int q = 0; q < DF / 4; q++) {
        float4 xv = __ldg(xp + q);
        float vals[4] = {xv.x, xv.y, xv.z, xv.w};
        #pragma unroll
        for (int c = 0; c < 4; c++) {
            int k = q * 4 + c;
            unsigned long long xx = pk2(vals[c], vals[c]);
            const ulonglong2* wrow = (const ulonglong2*)(sW1 + k * 32);
            #pragma unroll
            for (int m = 0; m < 8; m++) {
                ulonglong2 wv = wrow[m];
                acc[2 * m]     = fma2(xx, wv.x, acc[2 * m]);
                acc[2 * m + 1] = fma2(xx, wv.y, acc[2 * m + 1]);
            }
        }
    }

    __half2 hv[16];
    #pragma unroll
    for (int j = 0; j < 16; j++) {
        float a, b;
        upk2(acc[j], a, b);
        hv[j] = __floats2half2_rn(a, b);
    }
    uint4* dst = (uint4*)((char*)g_ABh + (long)node * 128 + half * 64);
    const uint4* src = (const uint4*)hv;
    #pragma unroll
    for (int m = 0; m < 4; m++) dst[m] = src[m];
}

// Edge kernel: 1 edge/thread, 32 edges/warp. Layer 2 runs on tensor cores:
// h (32x32 fp16, one row per edge) staged in smem -> ldmatrix -> 16x
// mma.sync.m16n8k16 against fp16 W2 (converted once per block). Epilogue
// adds b2, relu, dots with W3 on fragments, butterfly-reduces the 4-lane
// column split, and q==0 lanes scatter using per-warp (row, u[col]) meta.
__global__ __launch_bounds__(256, 2)
void edge_mlp_kernel(const void* __restrict__ ei_raw,
                     const float* __restrict__ u,
                     const float* __restrict__ W2g,
                     const float* __restrict__ b2g,
                     const float* __restrict__ W3g,
                     const float* __restrict__ b3g,
                     float* __restrict__ out)
{
    __shared__ __align__(16) char sW2h[HID * HSTR];        // 2.5 KB fp16 W2
    __shared__ __align__(16) char sH[8 * 32 * HSTR];       // 20 KB h staging
    __shared__ int2 sMeta[256];                            // (row, u[col]) per edge

    int tid = threadIdx.x;
    // Convert W2 -> fp16 into smem, [k][n] layout, row stride HSTR.
    for (int i = tid; i < HID * HID; i += 256) {
        int k = i >> 5, n = i & 31;
        *(__half*)(sW2h + k * HSTR + n * 2) = __float2half_rn(__ldg(W2g + i));
    }
    __syncthreads();

    int e = blockIdx.x * 256 + tid;
    if (e >= NE) return;               // warp-uniform: NE % 32 == 0
    int lane = tid & 31;
    int wid  = tid >> 5;

    int r, c;
    if (g_idx_is64) {
        const long long* ei = (const long long*)ei_raw;
        r = (int)__ldg(ei + e);
        c = (int)__ldg(ei + NE + e);
    } else {
        const int* ei = (const int*)ei_raw;
        r = __ldg(ei + e);
        c = __ldg(ei + NE + e);
    }
    r = min(max(r, 0), NN - 1);
    c = min(max(c, 0), NN - 1);

    float uc = __ldg(u + c);
    sMeta[wid * 32 + lane] = make_int2(r, __float_as_int(uc));

    // gather + fold -> h row (32 fp16 = 16 half2)
    const char* ab = (const char*)g_ABh;
    const uint4* ap = (const uint4*)(ab + (long)r * 128);
    const uint4* bp = (const uint4*)(ab + (long)c * 128 + 64);
    uint4 ra[4], rb[4];
    #pragma unroll
    for (int m = 0; m < 4; m++) { ra[m] = __ldg(ap + m); rb[m] = __ldg(bp + m); }

    const __half2 z2 = __half2half2(__ushort_as_half(0));
    char* hwarp = sH + wid * (32 * HSTR);
    unsigned int hrow = smem_u32(hwarp) + lane * HSTR;
    #pragma unroll
    for (int m = 0; m < 4; m++) {
        const __half2* ah = (const __half2*)&ra[m];
        const __half2* bh = (const __half2*)&rb[m];
        unsigned h0 = h2u(__hmax2(__hadd2(ah[0], bh[0]), z2));
        unsigned h1 = h2u(__hmax2(__hadd2(ah[1], bh[1]), z2));
        unsigned h2v = h2u(__hmax2(__hadd2(ah[2], bh[2]), z2));
        unsigned h3 = h2u(__hmax2(__hadd2(ah[3], bh[3]), z2));
        asm volatile("st.shared.v4.b32 [%0], {%1,%2,%3,%4};"
                     :: "r"(hrow + m * 16), "r"(h0), "r"(h1), "r"(h2v), "r"(h3)
                     : "memory");
    }
    __syncwarp();

    unsigned int hbase  = smem_u32(hwarp);
    unsigned int w2base = smem_u32(sW2h);

    // A fragments: [M][K][4], 16x16 tiles of h via ldmatrix.x4.
    unsigned afr[2][2][4];
    #pragma unroll
    for (int M = 0; M < 2; M++) {
        #pragma unroll
        for (int K = 0; K < 2; K++) {
            int row = M * 16 + (lane & 7) + ((lane >> 3) & 1) * 8;
            int kb  = K * 16 + ((lane >> 4) & 1) * 8;
            unsigned int addr = hbase + row * HSTR + kb * 2;
            asm volatile("ldmatrix.sync.aligned.m8n8.x4.shared.b16 "
                         "{%0,%1,%2,%3}, [%4];"
                         : "=r"(afr[M][K][0]), "=r"(afr[M][K][1]),
                           "=r"(afr[M][K][2]), "=r"(afr[M][K][3])
                         : "r"(addr));
        }
    }

    // B fragments: [K][N][2] from W2 via ldmatrix.x4.trans (two n-tiles per call).
    unsigned bfr[2][4][2];
    #pragma unroll
    for (int K = 0; K < 2; K++) {
        #pragma unroll
        for (int Np = 0; Np < 2; Np++) {          // n-pair: tiles 2Np, 2Np+1
            int krow = K * 16 + (lane & 7) + ((lane >> 3) & 1) * 8;
            int nb   = Np * 16 + ((lane >> 4) & 1) * 8;
            unsigned int addr = w2base + krow * HSTR + nb * 2;
            unsigned r0, r1, r2, r3;
            asm volatile("ldmatrix.sync.aligned.m8n8.x4.trans.shared.b16 "
                         "{%0,%1,%2,%3}, [%4];"
                         : "=r"(r0), "=r"(r1), "=r"(r2), "=r"(r3)
                         : "r"(addr));
            bfr[K][2 * Np][0]     = r0; bfr[K][2 * Np][1]     = r1;
            bfr[K][2 * Np + 1][0] = r2; bfr[K][2 * Np + 1][1] = r3;
        }
    }

    // 16x mma.sync: d[M][N] (m16n8, fp32) = sum_K A[M][K] * B[K][N]
    float d[2][4][4];
    #pragma unroll
    for (int M = 0; M < 2; M++)
        #pragma unroll
        for (int N = 0; N < 4; N++) {
            #pragma unroll
            for (int i = 0; i < 4; i++) d[M][N][i] = 0.0f;
            #pragma unroll
            for (int K = 0; K < 2; K++)
                asm volatile(
                    "mma.sync.aligned.m16n8k16.row.col.f32.f16.f16.f32 "
                    "{%0,%1,%2,%3}, {%4,%5,%6,%7}, {%8,%9}, {%0,%1,%2,%3};"
                    : "+f"(d[M][N][0]), "+f"(d[M][N][1]),
                      "+f"(d[M][N][2]), "+f"(d[M][N][3])
                    : "r"(afr[M][K][0]), "r"(afr[M][K][1]),
                      "r"(afr[M][K][2]), "r"(afr[M][K][3]),
                      "r"(bfr[K][N][0]), "r"(bfr[K][N][1]));
        }

    // Epilogue: thread (lane) holds cols c0=N*8+2q, c0+1 for q=lane&3,
    // rows M*16 + lane/4 (d0,d1) and +8 (d2,d3).
    int q = lane & 3;
    float2 b2v[4], w3v[4];
    #pragma unroll
    for (int N = 0; N < 4; N++) {
        b2v[N] = __ldg((const float2*)b2g + (N * 4 + q));
        w3v[N] = __ldg((const float2*)W3g + (N * 4 + q));
    }
    float b3v = __ldg(b3g);

    #pragma unroll
    for (int M = 0; M < 2; M++) {
        float wA = 0.0f, wB = 0.0f;
        #pragma unroll
        for (int N = 0; N < 4; N++) {
            wA = fmaf(fmaxf(d[M][N][0] + b2v[N].x, 0.0f), w3v[N].x, wA);
            wA = fmaf(fmaxf(d[M][N][1] + b2v[N].y, 0.0f), w3v[N].y, wA);
            wB = fmaf(fmaxf(d[M][N][2] + b2v[N].x, 0.0f), w3v[N].x, wB);
            wB = fmaf(fmaxf(d[M][N][3] + b2v[N].y, 0.0f), w3v[N].y, wB);
        }
        wA += __shfl_xor_sync(0xFFFFFFFFu, wA, 1);
        wA += __shfl_xor_sync(0xFFFFFFFFu, wA, 2);
        wB += __shfl_xor_sync(0xFFFFFFFFu, wB, 1);
        wB += __shfl_xor_sync(0xFFFFFFFFu, wB, 2);
        if (q == 0) {
            int rowA = M * 16 + (lane >> 2);
            int rowB = rowA + 8;
            int2 mA = sMeta[wid * 32 + rowA];
            int2 mB = sMeta[wid * 32 + rowB];
            atomicAdd(out + mA.x, (wA + b3v) * __int_as_float(mA.y));
            atomicAdd(out + mB.x, (wB + b3v) * __int_as_float(mB.y));
        }
    }
}

extern "C" void kernel_launch(void* const* d_in, const int* in_sizes, int n_in,
                              void* d_out, int out_size) {
    const float* x  = (const float*)d_in[0];
    const void*  ei = d_in[1];
    const float* u  = (const float*)d_in[2];
    const float* W1 = (const float*)d_in[3];
    const float* b1 = (const float*)d_in[4];
    const float* W2 = (const float*)d_in[5];
    const float* b2 = (const float*)d_in[6];
    const float* W3 = (const float*)d_in[7];
    const float* b3 = (const float*)d_in[8];
    float* out = (float*)d_out;

    dim3 gg((NN + 255) / 256, 2);
    node_gemm_kernel<<<gg, 256>>>((const float4*)x, W1, b1,
                                  (const long long*)ei, out);

    edge_mlp_kernel<<<(NE + 255) / 256, 256>>>(ei, u, W2, b2, W3, b3, out);
}

// round 17
// speedup vs baseline: 1.6888x; 1.3409x over previous
#include <cuda_runtime.h>
#include <cuda_fp16.h>

#define NE 1200000
#define NN 50000
#define DF 64
#define HID 32
#define HSTR 80   // smem row stride (bytes): 16B-aligned, conflict-light for LDSM

__device__ int g_idx_is64;

// fp16 per-node partials, one 128-byte line per node:
//   bytes [0,64)   : A'[n] = x[n]@W1[0:64] + b1   (32 fp16)
//   bytes [64,128) : B[n]  = x[n]@W1[64:128]      (32 fp16)
__device__ __align__(128) __half g_ABh[NN * 64];   // 6.4 MB (L2-resident)

// ---- packed f32x2 helpers (node_gemm only) ----
__device__ __forceinline__ unsigned long long pk2(float a, float b) {
    unsigned long long r;
    asm("mov.b64 %0, {%1, %2};" : "=l"(r) : "f"(a), "f"(b));
    return r;
}
__device__ __forceinline__ void upk2(unsigned long long v, float& a, float& b) {
    asm("mov.b64 {%0, %1}, %2;" : "=f"(a), "=f"(b) : "l"(v));
}
__device__ __forceinline__ unsigned long long fma2(unsigned long long a,
                                                   unsigned long long b,
                                                   unsigned long long c) {
    unsigned long long d;
    asm("fma.rn.f32x2 %0, %1, %2, %3;" : "=l"(d) : "l"(a), "l"(b), "l"(c));
    return d;
}
__device__ __forceinline__ unsigned int smem_u32(const void* p) {
    unsigned int a;
    asm("{ .reg .u64 t; cvta.to.shared.u64 t, %1; cvt.u32.u64 %0, t; }"
        : "=r"(a) : "l"(p));
    return a;
}
__device__ __forceinline__ unsigned int h2u(__half2 h) {
    unsigned int u;
    memcpy(&u, &h, 4);
    return u;
}

// Pre-pass (unchanged): per node per half; W1 staged in shared.
__global__ __launch_bounds__(256)
void node_gemm_kernel(const float4* __restrict__ x4,
                      const float* __restrict__ W1g,
                      const float* __restrict__ b1g,
                      const long long* __restrict__ ei,
                      float* __restrict__ out) {
    __shared__ __align__(16) float sW1[DF * HID];
    int half = blockIdx.y;

    for (int i = threadIdx.x; i < DF * HID / 4; i += blockDim.x)
        ((float4*)sW1)[i] = ((const float4*)W1g)[half * (DF * HID / 4) + i];
    __syncthreads();

    int node = blockIdx.x * blockDim.x + threadIdx.x;
    if (half == 0 && node < NN) out[node] = 0.0f;
    if (half == 0 && node == 0) {
        int ok64 = 1;
        for (int k = 0; k < 8; k++) {
            long long v = ei[k];
            if (v < 0 || v >= NN) ok64 = 0;
        }
        g_idx_is64 = ok64;
    }
    if (node >= NN) return;

    unsigned long long acc[16];
    if (half == 0) {
        const float2* b1p = (const float2*)b1g;
        #pragma unroll
        for (int j = 0; j < 16; j++) {
            float2 b = __ldg(b1p + j);
            acc[j] = pk2(b.x, b.y);
        }
    } else {
        #pragma unroll
        for (int j = 0; j < 16; j++) acc[j] = 0ULL;
    }

    const float4* xp = x4 + (long)node * (DF / 4);
    #pragma unroll 4
    for (int q = 0; q < DF / 4; q++) {
        float4 xv = __ldg(xp + q);
        float vals[4] = {xv.x, xv.y, xv.z, xv.w};
        #pragma unroll
        for (int c = 0; c < 4; c++) {
            int k = q * 4 + c;
            unsigned long long xx = pk2(vals[c], vals[c]);
            const ulonglong2* wrow = (const ulonglong2*)(sW1 + k * 32);
            #pragma unroll
            for (int m = 0; m < 8; m++) {
                ulonglong2 wv = wrow[m];
                acc[2 * m]     = fma2(xx, wv.x, acc[2 * m]);
                acc[2 * m + 1] = fma2(xx, wv.y, acc[2 * m + 1]);
            }
        }
    }

    __half2 hv[16];
    #pragma unroll
    for (int j = 0; j < 16; j++) {
        float a, b;
        upk2(acc[j], a, b);
        hv[j] = __floats2half2_rn(a, b);
    }
    uint4* dst = (uint4*)((char*)g_ABh + (long)node * 128 + half * 64);
    const uint4* src = (const uint4*)hv;
    #pragma unroll
    for (int m = 0; m < 4; m++) dst[m] = src[m];
}

// Edge kernel: 1 edge/thread, 32 edges/warp, tensor-core layer 2.
// NEW: warp-cooperative gather — 4 lanes fetch one 64B node-half (16B each),
// so each LDG.128 serves 8 edges and touches only 8 lines (4x fewer L1tex
// wavefronts than per-thread gathers). Indices come via warp shuffles.
__global__ __launch_bounds__(256, 3)
void edge_mlp_kernel(const void* __restrict__ ei_raw,
                     const float* __restrict__ u,
                     const float* __restrict__ W2g,
                     const float* __restrict__ b2g,
                     const float* __restrict__ W3g,
                     const float* __restrict__ b3g,
                     float* __restrict__ out)
{
    __shared__ __align__(16) char sW2h[HID * HSTR];        // 2.5 KB fp16 W2
    __shared__ __align__(16) char sH[8 * 32 * HSTR];       // 20 KB h staging
    __shared__ int2 sMeta[256];                            // (row, u[col]) per edge

    int tid = threadIdx.x;
    for (int i = tid; i < HID * HID; i += 256) {
        int k = i >> 5, n = i & 31;
        *(__half*)(sW2h + k * HSTR + n * 2) = __float2half_rn(__ldg(W2g + i));
    }
    __syncthreads();

    int e = blockIdx.x * 256 + tid;
    if (e >= NE) return;               // warp-uniform: NE % 32 == 0
    int lane = tid & 31;
    int wid  = tid >> 5;

    int r, c;
    if (g_idx_is64) {
        const long long* ei = (const long long*)ei_raw;
        r = (int)__ldg(ei + e);
        c = (int)__ldg(ei + NE + e);
    } else {
        const int* ei = (const int*)ei_raw;
        r = __ldg(ei + e);
        c = __ldg(ei + NE + e);
    }
    r = min(max(r, 0), NN - 1);
    c = min(max(c, 0), NN - 1);

    float uc = __ldg(u + c);
    sMeta[wid * 32 + lane] = make_int2(r, __float_as_int(uc));

    // ---- cooperative gather + fold + stage ----
    const char* ab = (const char*)g_ABh;
    const __half2 z2 = __half2half2(__ushort_as_half(0));
    char* hwarp = sH + wid * (32 * HSTR);
    unsigned int hbase = smem_u32(hwarp);
    int grp = lane >> 2;               // which of 8 edges this lane serves
    int q   = lane & 3;                // 16B quarter within the 64B half

    #pragma unroll
    for (int i = 0; i < 4; i++) {      // 8 edges per iteration
        int src = i * 8 + grp;
        int rg = __shfl_sync(0xFFFFFFFFu, r, src);
        int cg = __shfl_sync(0xFFFFFFFFu, c, src);
        uint4 av = __ldg((const uint4*)(ab + (long)rg * 128 + q * 16));
        uint4 bv = __ldg((const uint4*)(ab + (long)cg * 128 + 64 + q * 16));
        const __half2* ah = (const __half2*)&av;
        const __half2* bh = (const __half2*)&bv;
        unsigned h0 = h2u(__hmax2(__hadd2(ah[0], bh[0]), z2));
        unsigned h1 = h2u(__hmax2(__hadd2(ah[1], bh[1]), z2));
        unsigned h2v = h2u(__hmax2(__hadd2(ah[2], bh[2]), z2));
        unsigned h3 = h2u(__hmax2(__hadd2(ah[3], bh[3]), z2));
        asm volatile("st.shared.v4.b32 [%0], {%1,%2,%3,%4};"
                     :: "r"(hbase + (unsigned)(i * 8 + grp) * HSTR + q * 16),
                        "r"(h0), "r"(h1), "r"(h2v), "r"(h3)
                     : "memory");
    }
    __syncwarp();

    unsigned int w2base = smem_u32(sW2h);

    // A fragments: [M][K][4], 16x16 tiles of h via ldmatrix.x4.
    unsigned afr[2][2][4];
    #pragma unroll
    for (int M = 0; M < 2; M++) {
        #pragma unroll
        for (int K = 0; K < 2; K++) {
            int row = M * 16 + (lane & 7) + ((lane >> 3) & 1) * 8;
            int kb  = K * 16 + ((lane >> 4) & 1) * 8;
            unsigned int addr = hbase + row * HSTR + kb * 2;
            asm volatile("ldmatrix.sync.aligned.m8n8.x4.shared.b16 "
                         "{%0,%1,%2,%3}, [%4];"
                         : "=r"(afr[M][K][0]), "=r"(afr[M][K][1]),
                           "=r"(afr[M][K][2]), "=r"(afr[M][K][3])
                         : "r"(addr));
        }
    }

    // B fragments: [K][N][2] from W2 via ldmatrix.x4.trans.
    unsigned bfr[2][4][2];
    #pragma unroll
    for (int K = 0; K < 2; K++) {
        #pragma unroll
        for (int Np = 0; Np < 2; Np++) {
            int krow = K * 16 + (lane & 7) + ((lane >> 3) & 1) * 8;
            int nb   = Np * 16 + ((lane >> 4) & 1) * 8;
            unsigned int addr = w2base + krow * HSTR + nb * 2;
            unsigned r0, r1, r2, r3;
            asm volatile("ldmatrix.sync.aligned.m8n8.x4.trans.shared.b16 "
                         "{%0,%1,%2,%3}, [%4];"
                         : "=r"(r0), "=r"(r1), "=r"(r2), "=r"(r3)
                         : "r"(addr));
            bfr[K][2 * Np][0]     = r0; bfr[K][2 * Np][1]     = r1;
            bfr[K][2 * Np + 1][0] = r2; bfr[K][2 * Np + 1][1] = r3;
        }
    }

    // 16x mma.sync: d[M][N] (m16n8, fp32) = sum_K A[M][K] * B[K][N]
    float d[2][4][4];
    #pragma unroll
    for (int M = 0; M < 2; M++)
        #pragma unroll
        for (int N = 0; N < 4; N++) {
            #pragma unroll
            for (int i = 0; i < 4; i++) d[M][N][i] = 0.0f;
            #pragma unroll
            for (int K = 0; K < 2; K++)
                asm volatile(
                    "mma.sync.aligned.m16n8k16.row.col.f32.f16.f16.f32 "
                    "{%0,%1,%2,%3}, {%4,%5,%6,%7}, {%8,%9}, {%0,%1,%2,%3};"
                    : "+f"(d[M][N][0]), "+f"(d[M][N][1]),
                      "+f"(d[M][N][2]), "+f"(d[M][N][3])
                    : "r"(afr[M][K][0]), "r"(afr[M][K][1]),
                      "r"(afr[M][K][2]), "r"(afr[M][K][3]),
                      "r"(bfr[K][N][0]), "r"(bfr[K][N][1]));
        }

    // Epilogue: +b2, relu, dot W3, butterfly-reduce, q==0 lanes scatter.
    int qq = lane & 3;
    float2 b2v[4], w3v[4];
    #pragma unroll
    for (int N = 0; N < 4; N++) {
        b2v[N] = __ldg((const float2*)b2g + (N * 4 + qq));
        w3v[N] = __ldg((const float2*)W3g + (N * 4 + qq));
    }
    float b3v = __ldg(b3g);

    #pragma unroll
    for (int M = 0; M < 2; M++) {
        float wA = 0.0f, wB = 0.0f;
        #pragma unroll
        for (int N = 0; N < 4; N++) {
            wA = fmaf(fmaxf(d[M][N][0] + b2v[N].x, 0.0f), w3v[N].x, wA);
            wA = fmaf(fmaxf(d[M][N][1] + b2v[N].y, 0.0f), w3v[N].y, wA);
            wB = fmaf(fmaxf(d[M][N][2] + b2v[N].x, 0.0f), w3v[N].x, wB);
            wB = fmaf(fmaxf(d[M][N][3] + b2v[N].y, 0.0f), w3v[N].y, wB);
        }
        wA += __shfl_xor_sync(0xFFFFFFFFu, wA, 1);
        wA += __shfl_xor_sync(0xFFFFFFFFu, wA, 2);
        wB += __shfl_xor_sync(0xFFFFFFFFu, wB, 1);
        wB += __shfl_xor_sync(0xFFFFFFFFu, wB, 2);
        if (qq == 0) {
            int rowA = M * 16 + (lane >> 2);
            int rowB = rowA + 8;
            int2 mA = sMeta[wid * 32 + rowA];
            int2 mB = sMeta[wid * 32 + rowB];
            atomicAdd(out + mA.x, (wA + b3v) * __int_as_float(mA.y));
            atomicAdd(out + mB.x, (wB + b3v) * __int_as_float(mB.y));
        }
    }
}

extern "C" void kernel_launch(void* const* d_in, const int* in_sizes, int n_in,
                              void* d_out, int out_size) {
    const float* x  = (const float*)d_in[0];
    const void*  ei = d_in[1];
    const float* u  = (const float*)d_in[2];
    const float* W1 = (const float*)d_in[3];
    const float* b1 = (const float*)d_in[4];
    const float* W2 = (const float*)d_in[5];
    const float* b2 = (const float*)d_in[6];
    const float* W3 = (const float*)d_in[7];
    const float* b3 = (const float*)d_in[8];
    float* out = (float*)d_out;

    dim3 gg((NN + 255) / 256, 2);
    node_gemm_kernel<<<gg, 256>>>((const float4*)x, W1, b1,
                                  (const long long*)ei, out);

    edge_mlp_kernel<<<(NE + 255) / 256, 256>>>(ei, u, W2, b2, W3, b3, out);
}